// round 11
// baseline (speedup 1.0000x reference)
#include <cuda_runtime.h>
#include <cuda_fp16.h>
#include <math.h>
#include <stdint.h>

#define T_TOK   16384
#define H_DIM   2048
#define E_DIM   64
#define BM      64
#define KC      32
#define NSTG    (H_DIM / KC)            // 64
#define NBLK    (T_TOK / BM)            // 256
#define NTHR    256

#define W_OFF   0
#define I_OFF   32768
#define L_OFF   65536
#define Z_OFF   1114112
#define LB_OFF  1114113

#define PITCH   80                      // 64B (32 fp16) + 16B pad per row
#define LTILE   (BM * PITCH)            // 5120 B per limb tile
#define ABUF    (2 * LTILE)             // 10240 B A image (hi|mid)
#define BIMG    (2 * LTILE)             // 10240 B B image (hi|mid)
#define BCHUNKS (BIMG / 16)             // 640
#define DYN_B   (2 * ABUF + 3 * BIMG)   // 51200 -> 3 CTAs/SM (smem)

__device__ __align__(256) unsigned char g_wlimb[NSTG * BIMG];  // 640 KB
__device__ float g_partials[NBLK * 3 * E_DIM];
__device__ int   g_done = 0;

__device__ __forceinline__ uint32_t smem_u32(const void* p) {
    uint32_t a;
    asm("{ .reg .u64 t; cvta.to.shared.u64 t, %1; cvt.u32.u64 %0, t; }" : "=r"(a) : "l"(p));
    return a;
}
__device__ __forceinline__ void sts64(uint32_t a, uint32_t x, uint32_t y) {
    asm volatile("st.shared.v2.b32 [%0], {%1, %2};" :: "r"(a), "r"(x), "r"(y));
}
#define LDSM_X4(r0, r1, r2, r3, addr)                                         \
    asm volatile("ldmatrix.sync.aligned.m8n8.x4.shared.b16 {%0,%1,%2,%3}, [%4];" \
                 : "=r"(r0), "=r"(r1), "=r"(r2), "=r"(r3) : "r"(addr))
#define MMA16816(d, a, b)                                                     \
    asm volatile("mma.sync.aligned.m16n8k16.row.col.f32.f16.f16.f32 "         \
                 "{%0,%1,%2,%3}, {%4,%5,%6,%7}, {%8,%9}, {%0,%1,%2,%3};"      \
                 : "+f"((d)[0]), "+f"((d)[1]), "+f"((d)[2]), "+f"((d)[3])     \
                 : "r"((a)[0]), "r"((a)[1]), "r"((a)[2]), "r"((a)[3]),        \
                   "r"((b)[0]), "r"((b)[1]))
#define CP_ASYNC16(dst, src)                                                  \
    asm volatile("cp.async.ca.shared.global [%0], [%1], 16;" :: "r"(dst), "l"(src))
#define CP_COMMIT()  asm volatile("cp.async.commit_group;" ::: "memory")
#define CP_WAIT(n)   asm volatile("cp.async.wait_group %0;" :: "n"(n) : "memory")

// 2-limb fp16 split: h+m ~ x to 2^-22 rel; residual subtraction exact.
__device__ __forceinline__ void split2(float x0, float x1, uint32_t& h, uint32_t& m) {
    __half2 h2 = __floats2half2_rn(x0, x1);
    h = *reinterpret_cast<uint32_t*>(&h2);
    float2 hf = __half22float2(h2);
    __half2 m2 = __floats2half2_rn(x0 - hf.x, x1 - hf.y);
    m = *reinterpret_cast<uint32_t*>(&m2);
}

// ---- W limb precompute: [E,H] fp32 -> per-stage f16 limb images (PITCH 80) ----
__global__ __launch_bounds__(256, 4)
void wsplit_kernel(const float* __restrict__ W)
{
    const int f  = blockIdx.x * 256 + threadIdx.x;   // float4 id, 0..32767
    const int e  = f >> 9, c = f & 511;
    const int st = c >> 3, q = c & 7;                // stage, f4-within-stage-row
    float4 v = *(const float4*)(W + (size_t)e * H_DIM + c * 4);
    uint32_t h0, m0, h1, m1;
    split2(v.x, v.y, h0, m0);
    split2(v.z, v.w, h1, m1);
    unsigned char* img = g_wlimb + (size_t)st * BIMG;
    const uint32_t off = (uint32_t)(e * PITCH + q * 8);
    *(uint2*)(img + off)         = make_uint2(h0, h1);
    *(uint2*)(img + LTILE + off) = make_uint2(m0, m1);
}

__global__ __launch_bounds__(NTHR, 3)
void fused_router_kernel(const float* __restrict__ A, float* __restrict__ out)
{
    extern __shared__ __align__(16) unsigned char dynsm[];
    const uint32_t sbase = smem_u32(dynsm);          // [Abuf0|Abuf1|B0|B1|B2]
    const uint32_t bbase = sbase + 2 * ABUF;

    const int tid  = threadIdx.x;
    const int wid  = tid >> 5;
    const int lane = tid & 31;
    const int row0 = blockIdx.x * BM;

    // A load map: 64 rows x 32 floats = 512 f4 -> 2 per thread
    int arow[2], ac4[2];
#pragma unroll
    for (int j = 0; j < 2; j++) { int f = tid + j * NTHR; arow[j] = f >> 3; ac4[j] = f & 7; }

    float4 va[2];

    // ---- prologue ----
#pragma unroll
    for (int j = 0; j < 3; j++) {        // B0
        uint32_t cid = (uint32_t)tid + j * NTHR;
        if (cid < BCHUNKS) CP_ASYNC16(bbase + cid * 16, g_wlimb + cid * 16);
    }
    CP_COMMIT();
#pragma unroll
    for (int j = 0; j < 2; j++)          // A0 -> regs
        va[j] = *(const float4*)(A + (size_t)(row0 + arow[j]) * H_DIM + ac4[j] * 4);
#pragma unroll
    for (int j = 0; j < 2; j++) {        // A0 -> Abuf0
        uint32_t h0, m0, h1, m1;
        split2(va[j].x, va[j].y, h0, m0);
        split2(va[j].z, va[j].w, h1, m1);
        const uint32_t off = (uint32_t)(arow[j] * PITCH + ac4[j] * 8);
        sts64(sbase + off, h0, h1);
        sts64(sbase + LTILE + off, m0, m1);
    }
#pragma unroll
    for (int j = 0; j < 3; j++) {        // B1
        uint32_t cid = (uint32_t)tid + j * NTHR;
        if (cid < BCHUNKS) CP_ASYNC16(bbase + BIMG + cid * 16, g_wlimb + BIMG + cid * 16);
    }
    CP_COMMIT();
#pragma unroll
    for (int j = 0; j < 2; j++)          // A1 -> regs
        va[j] = *(const float4*)(A + (size_t)(row0 + arow[j]) * H_DIM + KC + ac4[j] * 4);

    // warp tile 16x32: mstrip = wid&3, nhalf = wid>>2
    const int mstrip = wid & 3, nhalf = wid >> 2;
    const uint32_t a_off = (uint32_t)((mstrip * 16 + (lane & 15)) * PITCH + (lane >> 4) * 16);
    const uint32_t b_off = (uint32_t)((nhalf * 32 + (lane & 7) + ((lane >> 4) & 1) * 8) * PITCH
                                      + ((lane >> 3) & 1) * 16);

    float acc[16];
#pragma unroll
    for (int i = 0; i < 16; i++) acc[i] = 0.0f;

    for (int i = 0; i < NSTG; i++) {
        if (i == NSTG - 1) CP_WAIT(0); else CP_WAIT(1);
        __syncthreads();

        // producer: B_{i+2} cp.async, A_{i+1} split->STS, A_{i+2} LDG
        if (i + 2 < NSTG) {
            const unsigned char* gB = g_wlimb + (size_t)(i + 2) * BIMG;
            const uint32_t dst = bbase + (uint32_t)((i + 2) % 3) * BIMG;
#pragma unroll
            for (int j = 0; j < 3; j++) {
                uint32_t cid = (uint32_t)tid + j * NTHR;
                if (cid < BCHUNKS) CP_ASYNC16(dst + cid * 16, gB + cid * 16);
            }
            CP_COMMIT();
        }
        if (i + 1 < NSTG) {
            const uint32_t da = sbase + (uint32_t)((i + 1) & 1) * ABUF;
#pragma unroll
            for (int j = 0; j < 2; j++) {
                uint32_t h0, m0, h1, m1;
                split2(va[j].x, va[j].y, h0, m0);
                split2(va[j].z, va[j].w, h1, m1);
                const uint32_t off = (uint32_t)(arow[j] * PITCH + ac4[j] * 8);
                sts64(da + off, h0, h1);
                sts64(da + LTILE + off, m0, m1);
            }
            if (i + 2 < NSTG) {
                const int kt = (i + 2) * KC;
#pragma unroll
                for (int j = 0; j < 2; j++)
                    va[j] = *(const float4*)(A + (size_t)(row0 + arow[j]) * H_DIM + kt + ac4[j] * 4);
            }
        }

        // consumer: 2 k16 steps on current buffers
        const uint32_t sa = sbase + (uint32_t)(i & 1) * ABUF;
        const uint32_t sb = bbase + (uint32_t)(i % 3) * BIMG;
#pragma unroll
        for (int ks = 0; ks < 2; ks++) {
            uint32_t aH[4], aM[4], bH[8], bM[8];
            LDSM_X4(aH[0], aH[1], aH[2], aH[3], sa + a_off + ks * 32);
            LDSM_X4(aM[0], aM[1], aM[2], aM[3], sa + LTILE + a_off + ks * 32);
#pragma unroll
            for (int np = 0; np < 2; np++) {
                LDSM_X4(bH[np * 4 + 0], bH[np * 4 + 1], bH[np * 4 + 2], bH[np * 4 + 3],
                        sb + (uint32_t)(np * 16 * PITCH) + b_off + ks * 32);
                LDSM_X4(bM[np * 4 + 0], bM[np * 4 + 1], bM[np * 4 + 2], bM[np * 4 + 3],
                        sb + LTILE + (uint32_t)(np * 16 * PITCH) + b_off + ks * 32);
            }
            // term-outer: 4 independent acc chains per term (mm dropped, ~2^-22)
#pragma unroll
            for (int nt = 0; nt < 4; nt++) MMA16816(acc + nt * 4, aH, bH + nt * 2);
#pragma unroll
            for (int nt = 0; nt < 4; nt++) MMA16816(acc + nt * 4, aH, bM + nt * 2);
#pragma unroll
            for (int nt = 0; nt < 4; nt++) MMA16816(acc + nt * 4, aM, bH + nt * 2);
        }
    }
    __syncthreads();

    // ---- fused epilogue ----
    float* fsm = (float*)dynsm;                 // [64][68]
    int*   si1 = (int*)(fsm + 64 * 68);
    float* sp1 = (float*)(si1 + 64);
    int*   si2 = (int*)(sp1 + 64);
    float* sp2 = (float*)(si2 + 64);

    {
        const int mrow = mstrip * 16 + (lane >> 2);
        const int ncl  = nhalf * 32 + (lane & 3) * 2;
#pragma unroll
        for (int nt = 0; nt < 4; nt++) {
            *(float2*)&fsm[mrow * 68 + ncl + nt * 8] =
                make_float2(acc[nt * 4 + 0], acc[nt * 4 + 1]);
            *(float2*)&fsm[(mrow + 8) * 68 + ncl + nt * 8] =
                make_float2(acc[nt * 4 + 2], acc[nt * 4 + 3]);
        }
    }
    __syncthreads();

    if (tid < BM) {
        float lg[64];
#pragma unroll
        for (int c = 0; c < 64; c++) lg[c] = fsm[tid * 68 + c];
        float mx = lg[0];
#pragma unroll
        for (int c = 1; c < 64; c++) mx = fmaxf(mx, lg[c]);
        float se = 0.0f;
#pragma unroll
        for (int c = 0; c < 64; c++) se += expf(lg[c] - mx);
        float v1 = -INFINITY; int i1 = 0;
#pragma unroll
        for (int c = 0; c < 64; c++)
            if (lg[c] > v1) { v1 = lg[c]; i1 = c; }
        float v2 = -INFINITY; int i2 = 0;
#pragma unroll
        for (int c = 0; c < 64; c++)
            if (c != i1 && lg[c] > v2) { v2 = lg[c]; i2 = c; }

        const float p1 = expf(v1 - mx) / se;
        const float p2 = expf(v2 - mx) / se;
        const float inv = 1.0f / (p1 + p2);
        const int t = row0 + tid;
        out[W_OFF + (size_t)t * 2 + 0] = p1 * inv;
        out[W_OFF + (size_t)t * 2 + 1] = p2 * inv;
        out[I_OFF + (size_t)t * 2 + 0] = (float)i1;
        out[I_OFF + (size_t)t * 2 + 1] = (float)i2;
        si1[tid] = i1; sp1[tid] = p1;
        si2[tid] = i2; sp2[tid] = p2;
    }
    __syncthreads();

#pragma unroll
    for (int j = 0; j < 4; j++) {           // coalesced logits store: 1024 f4
        int u = j * NTHR + tid, r = u >> 4, c4 = (u & 15) * 4;
        float4 v = *(float4*)&fsm[r * 68 + c4];
        *(float4*)&out[L_OFF + (size_t)(row0 + r) * 64 + c4] = v;
    }

    if (tid < E_DIM) {                       // deterministic per-block partials
        float s1 = 0.0f, s2 = 0.0f, cc = 0.0f;
        for (int r = 0; r < BM; r++) {
            float v = fsm[r * 68 + tid];
            s1 += v;
            s2 = fmaf(v, v, s2);
            if (si1[r] == tid) cc += sp1[r];
            if (si2[r] == tid) cc += sp2[r];
        }
        const int b = blockIdx.x;
        g_partials[(b * 3 + 0) * E_DIM + tid] = s1;
        g_partials[(b * 3 + 1) * E_DIM + tid] = s2;
        g_partials[(b * 3 + 2) * E_DIM + tid] = cc;
    }

    // ---- fused finalize ----
    __syncthreads();
    __threadfence();
    __shared__ int s_last;
    if (tid == 0) s_last = (atomicAdd(&g_done, 1) == NBLK - 1) ? 1 : 0;
    __syncthreads();
    if (!s_last) return;
    __threadfence();

    float* red = (float*)dynsm;              // [2][3][64]
    {
        const int g = tid >> 6, e = tid & 63;
        if (g < 2) {
            float s1 = 0.0f, s2 = 0.0f, c = 0.0f;
            for (int b = g * 128; b < g * 128 + 128; b++) {
                s1 += g_partials[(b * 3 + 0) * E_DIM + e];
                s2 += g_partials[(b * 3 + 1) * E_DIM + e];
                c  += g_partials[(b * 3 + 2) * E_DIM + e];
            }
            red[(g * 3 + 0) * 64 + e] = s1;
            red[(g * 3 + 1) * 64 + e] = s2;
            red[(g * 3 + 2) * 64 + e] = c;
        }
    }
    __syncthreads();

    float* sv = red + 6 * 64;
    float* sf = sv + 64;
    if (tid < 64) {
        float s1 = 0.0f, s2 = 0.0f, c = 0.0f;
#pragma unroll
        for (int g = 0; g < 2; g++) {
            s1 += red[(g * 3 + 0) * 64 + tid];
            s2 += red[(g * 3 + 1) * 64 + tid];
            c  += red[(g * 3 + 2) * 64 + tid];
        }
        const float invT = 1.0f / (float)T_TOK;
        const float mean = s1 * invT;
        sv[tid] = s2 * invT - mean * mean;
        sf[tid] = c * invT;
    }
    __syncthreads();
    if (tid == 0) {
        float vsum = 0.0f, fsum = 0.0f;
        for (int i = 0; i < E_DIM; i++) { vsum += sv[i]; fsum += sf[i]; }
        out[Z_OFF] = (vsum / (float)E_DIM) * 0.001f;
        const float meanf = fsum / (float)E_DIM;
        float a2 = 0.0f;
        for (int i = 0; i < E_DIM; i++) {
            const float d = sf[i] - meanf;
            a2 = fmaf(d, d, a2);
        }
        out[LB_OFF] = (sqrtf(a2 / (float)(E_DIM - 1)) / (meanf + 1e-8f)) * 0.01f;
        g_done = 0;
    }
}

extern "C" void kernel_launch(void* const* d_in, const int* in_sizes, int n_in,
                              void* d_out, int out_size)
{
    const float* hs = (const float*)d_in[0];
    const float* W  = (const float*)d_in[1];
    if (n_in >= 2 && in_sizes[0] < in_sizes[1]) {
        const float* t = hs; hs = W; W = t;
    }
    float* out = (float*)d_out;
    cudaFuncSetAttribute(fused_router_kernel,
                         cudaFuncAttributeMaxDynamicSharedMemorySize, DYN_B);
    wsplit_kernel<<<128, 256>>>(W);
    fused_router_kernel<<<NBLK, NTHR, DYN_B>>>(hs, out);
}

// round 13
// speedup vs baseline: 1.0935x; 1.0935x over previous
#include <cuda_runtime.h>
#include <cuda_fp16.h>
#include <math.h>
#include <stdint.h>

#define T_TOK   16384
#define H_DIM   2048
#define E_DIM   64
#define BM      64
#define KC      64
#define NSTG    (H_DIM / KC)            // 32
#define NBLK    (T_TOK / BM)            // 256
#define NTHR    256

#define W_OFF   0
#define I_OFF   32768
#define L_OFF   65536
#define Z_OFF   1114112
#define LB_OFF  1114113

#define PITCH   144                     // 128B (64 fp16) + 16B pad per row
#define LTILE   (BM * PITCH)            // 9216 B per limb tile
#define ABUF    (2 * LTILE)             // 18432 B A image (hi|mid)
#define BIMG    (2 * LTILE)             // 18432 B B image (hi|mid)
#define BCHUNKS (BIMG / 16)             // 1152
#define DYN_B   (2 * ABUF + 3 * BIMG)   // 92160 -> 2 CTAs/SM

__device__ __align__(256) unsigned char g_wlimb[NSTG * BIMG];  // 576 KB
__device__ float g_partials[NBLK * 3 * E_DIM];
__device__ int   g_done = 0;

__device__ __forceinline__ uint32_t smem_u32(const void* p) {
    uint32_t a;
    asm("{ .reg .u64 t; cvta.to.shared.u64 t, %1; cvt.u32.u64 %0, t; }" : "=r"(a) : "l"(p));
    return a;
}
__device__ __forceinline__ void sts64(uint32_t a, uint32_t x, uint32_t y) {
    asm volatile("st.shared.v2.b32 [%0], {%1, %2};" :: "r"(a), "r"(x), "r"(y));
}
#define LDSM_X4(r0, r1, r2, r3, addr)                                         \
    asm volatile("ldmatrix.sync.aligned.m8n8.x4.shared.b16 {%0,%1,%2,%3}, [%4];" \
                 : "=r"(r0), "=r"(r1), "=r"(r2), "=r"(r3) : "r"(addr))
#define MMA16816(d, a, b)                                                     \
    asm volatile("mma.sync.aligned.m16n8k16.row.col.f32.f16.f16.f32 "         \
                 "{%0,%1,%2,%3}, {%4,%5,%6,%7}, {%8,%9}, {%0,%1,%2,%3};"      \
                 : "+f"((d)[0]), "+f"((d)[1]), "+f"((d)[2]), "+f"((d)[3])     \
                 : "r"((a)[0]), "r"((a)[1]), "r"((a)[2]), "r"((a)[3]),        \
                   "r"((b)[0]), "r"((b)[1]))
// f16-accumulate variant for the small correction terms
#define MMA16816H(d, a, b)                                                    \
    asm volatile("mma.sync.aligned.m16n8k16.row.col.f16.f16.f16.f16 "         \
                 "{%0,%1}, {%2,%3,%4,%5}, {%6,%7}, {%0,%1};"                  \
                 : "+r"((d)[0]), "+r"((d)[1])                                 \
                 : "r"((a)[0]), "r"((a)[1]), "r"((a)[2]), "r"((a)[3]),        \
                   "r"((b)[0]), "r"((b)[1]))
#define CP_ASYNC16(dst, src)                                                  \
    asm volatile("cp.async.ca.shared.global [%0], [%1], 16;" :: "r"(dst), "l"(src))
#define CP_COMMIT()  asm volatile("cp.async.commit_group;" ::: "memory")
#define CP_WAIT(n)   asm volatile("cp.async.wait_group %0;" :: "n"(n) : "memory")

// 2-limb fp16 split: h+m ~ x to 2^-22 rel; residual subtraction exact.
__device__ __forceinline__ void split2(float x0, float x1, uint32_t& h, uint32_t& m) {
    __half2 h2 = __floats2half2_rn(x0, x1);
    h = *reinterpret_cast<uint32_t*>(&h2);
    float2 hf = __half22float2(h2);
    __half2 m2 = __floats2half2_rn(x0 - hf.x, x1 - hf.y);
    m = *reinterpret_cast<uint32_t*>(&m2);
}

// ---- W limb precompute: [E,H] fp32 -> per-stage f16 limb images (PITCH 144) ----
__global__ __launch_bounds__(256, 4)
void wsplit_kernel(const float* __restrict__ W)
{
    const int f  = blockIdx.x * 256 + threadIdx.x;   // float4 id, 0..32767
    const int e  = f >> 9, c = f & 511;
    const int st = c >> 4, q = c & 15;
    float4 v = *(const float4*)(W + (size_t)e * H_DIM + c * 4);
    uint32_t h0, m0, h1, m1;
    split2(v.x, v.y, h0, m0);
    split2(v.z, v.w, h1, m1);
    unsigned char* img = g_wlimb + (size_t)st * BIMG;
    const uint32_t off = (uint32_t)(e * PITCH + q * 8);
    *(uint2*)(img + off)         = make_uint2(h0, h1);
    *(uint2*)(img + LTILE + off) = make_uint2(m0, m1);
}

__global__ __launch_bounds__(NTHR, 2)
void fused_router_kernel(const float* __restrict__ A, float* __restrict__ out)
{
    extern __shared__ __align__(16) unsigned char dynsm[];
    const uint32_t sbase = smem_u32(dynsm);          // [Abuf0|Abuf1|B0|B1|B2]
    const uint32_t bbase = sbase + 2 * ABUF;

    const int tid  = threadIdx.x;
    const int wid  = tid >> 5;
    const int lane = tid & 31;
    const int row0 = blockIdx.x * BM;

    // A load map: 64 rows x 64 floats = 1024 f4 -> 4 per thread
    int arow[4], ac4[4];
#pragma unroll
    for (int j = 0; j < 4; j++) { int f = tid + j * NTHR; arow[j] = f >> 4; ac4[j] = f & 15; }

    float4 va[4];

    // ---- prologue ----
#pragma unroll
    for (int j = 0; j < 5; j++) {        // B0
        uint32_t cid = (uint32_t)tid + j * NTHR;
        if (cid < BCHUNKS) CP_ASYNC16(bbase + cid * 16, g_wlimb + cid * 16);
    }
    CP_COMMIT();
#pragma unroll
    for (int j = 0; j < 4; j++)          // A0 -> regs
        va[j] = *(const float4*)(A + (size_t)(row0 + arow[j]) * H_DIM + ac4[j] * 4);
#pragma unroll
    for (int j = 0; j < 4; j++) {        // A0 -> Abuf0
        uint32_t h0, m0, h1, m1;
        split2(va[j].x, va[j].y, h0, m0);
        split2(va[j].z, va[j].w, h1, m1);
        const uint32_t off = (uint32_t)(arow[j] * PITCH + ac4[j] * 8);
        sts64(sbase + off, h0, h1);
        sts64(sbase + LTILE + off, m0, m1);
    }
#pragma unroll
    for (int j = 0; j < 5; j++) {        // B1
        uint32_t cid = (uint32_t)tid + j * NTHR;
        if (cid < BCHUNKS) CP_ASYNC16(bbase + BIMG + cid * 16, g_wlimb + BIMG + cid * 16);
    }
    CP_COMMIT();
#pragma unroll
    for (int j = 0; j < 4; j++)          // A1 -> regs
        va[j] = *(const float4*)(A + (size_t)(row0 + arow[j]) * H_DIM + KC + ac4[j] * 4);

    // warp tile 16x32: mstrip = wid&3, nhalf = wid>>2
    const int mstrip = wid & 3, nhalf = wid >> 2;
    const uint32_t a_off = (uint32_t)((mstrip * 16 + (lane & 15)) * PITCH + (lane >> 4) * 16);
    const uint32_t b_off = (uint32_t)((nhalf * 32 + (lane & 7) + ((lane >> 4) & 1) * 8) * PITCH
                                      + ((lane >> 3) & 1) * 16);

    float acc[16];
#pragma unroll
    for (int i = 0; i < 16; i++) acc[i] = 0.0f;
    uint32_t cacc[8];                    // f16x2 correction accumulators, 4 tiles
#pragma unroll
    for (int i = 0; i < 8; i++) cacc[i] = 0u;

    for (int i = 0; i < NSTG; i++) {
        if (i == NSTG - 1) CP_WAIT(0); else CP_WAIT(1);
        __syncthreads();

        // producer: B_{i+2} cp.async, A_{i+1} split->STS, A_{i+2} LDG
        if (i + 2 < NSTG) {
            const unsigned char* gB = g_wlimb + (size_t)(i + 2) * BIMG;
            const uint32_t dst = bbase + (uint32_t)((i + 2) % 3) * BIMG;
#pragma unroll
            for (int j = 0; j < 5; j++) {
                uint32_t cid = (uint32_t)tid + j * NTHR;
                if (cid < BCHUNKS) CP_ASYNC16(dst + cid * 16, gB + cid * 16);
            }
            CP_COMMIT();
        }
        if (i + 1 < NSTG) {
            const uint32_t da = sbase + (uint32_t)((i + 1) & 1) * ABUF;
#pragma unroll
            for (int j = 0; j < 4; j++) {
                uint32_t h0, m0, h1, m1;
                split2(va[j].x, va[j].y, h0, m0);
                split2(va[j].z, va[j].w, h1, m1);
                const uint32_t off = (uint32_t)(arow[j] * PITCH + ac4[j] * 8);
                sts64(da + off, h0, h1);
                sts64(da + LTILE + off, m0, m1);
            }
            if (i + 2 < NSTG) {
                const int kt = (i + 2) * KC;
#pragma unroll
                for (int j = 0; j < 4; j++)
                    va[j] = *(const float4*)(A + (size_t)(row0 + arow[j]) * H_DIM + kt + ac4[j] * 4);
            }
        }

        // consumer: 4 k16 steps on current buffers
        const uint32_t sa = sbase + (uint32_t)(i & 1) * ABUF;
        const uint32_t sb = bbase + (uint32_t)(i % 3) * BIMG;
#pragma unroll
        for (int ks = 0; ks < 4; ks++) {
            uint32_t aH[4], aM[4], bH[8], bM[8];
            LDSM_X4(aH[0], aH[1], aH[2], aH[3], sa + a_off + ks * 32);
            LDSM_X4(aM[0], aM[1], aM[2], aM[3], sa + LTILE + a_off + ks * 32);
#pragma unroll
            for (int np = 0; np < 2; np++) {
                LDSM_X4(bH[np * 4 + 0], bH[np * 4 + 1], bH[np * 4 + 2], bH[np * 4 + 3],
                        sb + (uint32_t)(np * 16 * PITCH) + b_off + ks * 32);
                LDSM_X4(bM[np * 4 + 0], bM[np * 4 + 1], bM[np * 4 + 2], bM[np * 4 + 3],
                        sb + LTILE + (uint32_t)(np * 16 * PITCH) + b_off + ks * 32);
            }
            // main term (f32 acc) + corrections (f16 acc, ~2^-11 of main)
#pragma unroll
            for (int nt = 0; nt < 4; nt++) MMA16816(acc + nt * 4, aH, bH + nt * 2);
#pragma unroll
            for (int nt = 0; nt < 4; nt++) MMA16816H(cacc + nt * 2, aH, bM + nt * 2);
#pragma unroll
            for (int nt = 0; nt < 4; nt++) MMA16816H(cacc + nt * 2, aM, bH + nt * 2);
        }
    }
    // merge f16 corrections into f32 accumulators
#pragma unroll
    for (int nt = 0; nt < 4; nt++) {
        float2 c0 = __half22float2(*reinterpret_cast<__half2*>(&cacc[nt * 2 + 0]));
        float2 c1 = __half22float2(*reinterpret_cast<__half2*>(&cacc[nt * 2 + 1]));
        acc[nt * 4 + 0] += c0.x; acc[nt * 4 + 1] += c0.y;
        acc[nt * 4 + 2] += c1.x; acc[nt * 4 + 3] += c1.y;
    }
    __syncthreads();

    // ---- fused epilogue ----
    float* fsm = (float*)dynsm;                 // [64][68]
    int*   si1 = (int*)(fsm + 64 * 68);
    float* sp1 = (float*)(si1 + 64);
    int*   si2 = (int*)(sp1 + 64);
    float* sp2 = (float*)(si2 + 64);

    {
        const int mrow = mstrip * 16 + (lane >> 2);
        const int ncl  = nhalf * 32 + (lane & 3) * 2;
#pragma unroll
        for (int nt = 0; nt < 4; nt++) {
            *(float2*)&fsm[mrow * 68 + ncl + nt * 8] =
                make_float2(acc[nt * 4 + 0], acc[nt * 4 + 1]);
            *(float2*)&fsm[(mrow + 8) * 68 + ncl + nt * 8] =
                make_float2(acc[nt * 4 + 2], acc[nt * 4 + 3]);
        }
    }
    __syncthreads();

    if (tid < BM) {
        float lg[64];
#pragma unroll
        for (int c = 0; c < 64; c++) lg[c] = fsm[tid * 68 + c];
        float mx = lg[0];
#pragma unroll
        for (int c = 1; c < 64; c++) mx = fmaxf(mx, lg[c]);
        float se = 0.0f;
#pragma unroll
        for (int c = 0; c < 64; c++) se += expf(lg[c] - mx);
        float v1 = -INFINITY; int i1 = 0;
#pragma unroll
        for (int c = 0; c < 64; c++)
            if (lg[c] > v1) { v1 = lg[c]; i1 = c; }
        float v2 = -INFINITY; int i2 = 0;
#pragma unroll
        for (int c = 0; c < 64; c++)
            if (c != i1 && lg[c] > v2) { v2 = lg[c]; i2 = c; }

        const float p1 = expf(v1 - mx) / se;
        const float p2 = expf(v2 - mx) / se;
        const float inv = 1.0f / (p1 + p2);
        const int t = row0 + tid;
        out[W_OFF + (size_t)t * 2 + 0] = p1 * inv;
        out[W_OFF + (size_t)t * 2 + 1] = p2 * inv;
        out[I_OFF + (size_t)t * 2 + 0] = (float)i1;
        out[I_OFF + (size_t)t * 2 + 1] = (float)i2;
        si1[tid] = i1; sp1[tid] = p1;
        si2[tid] = i2; sp2[tid] = p2;
    }
    __syncthreads();

#pragma unroll
    for (int j = 0; j < 4; j++) {           // coalesced logits store: 1024 f4
        int u = j * NTHR + tid, r = u >> 4, c4 = (u & 15) * 4;
        float4 v = *(float4*)&fsm[r * 68 + c4];
        *(float4*)&out[L_OFF + (size_t)(row0 + r) * 64 + c4] = v;
    }

    if (tid < E_DIM) {                       // deterministic per-block partials
        float s1 = 0.0f, s2 = 0.0f, cc = 0.0f;
        for (int r = 0; r < BM; r++) {
            float v = fsm[r * 68 + tid];
            s1 += v;
            s2 = fmaf(v, v, s2);
            if (si1[r] == tid) cc += sp1[r];
            if (si2[r] == tid) cc += sp2[r];
        }
        const int b = blockIdx.x;
        g_partials[(b * 3 + 0) * E_DIM + tid] = s1;
        g_partials[(b * 3 + 1) * E_DIM + tid] = s2;
        g_partials[(b * 3 + 2) * E_DIM + tid] = cc;
    }

    // ---- fused finalize ----
    __syncthreads();
    __threadfence();
    __shared__ int s_last;
    if (tid == 0) s_last = (atomicAdd(&g_done, 1) == NBLK - 1) ? 1 : 0;
    __syncthreads();
    if (!s_last) return;
    __threadfence();

    float* red = (float*)dynsm;              // [2][3][64]
    {
        const int g = tid >> 6, e = tid & 63;
        if (g < 2) {
            float s1 = 0.0f, s2 = 0.0f, c = 0.0f;
            for (int b = g * 128; b < g * 128 + 128; b++) {
                s1 += g_partials[(b * 3 + 0) * E_DIM + e];
                s2 += g_partials[(b * 3 + 1) * E_DIM + e];
                c  += g_partials[(b * 3 + 2) * E_DIM + e];
            }
            red[(g * 3 + 0) * 64 + e] = s1;
            red[(g * 3 + 1) * 64 + e] = s2;
            red[(g * 3 + 2) * 64 + e] = c;
        }
    }
    __syncthreads();

    float* sv = red + 6 * 64;
    float* sf = sv + 64;
    if (tid < 64) {
        float s1 = 0.0f, s2 = 0.0f, c = 0.0f;
#pragma unroll
        for (int g = 0; g < 2; g++) {
            s1 += red[(g * 3 + 0) * 64 + tid];
            s2 += red[(g * 3 + 1) * 64 + tid];
            c  += red[(g * 3 + 2) * 64 + tid];
        }
        const float invT = 1.0f / (float)T_TOK;
        const float mean = s1 * invT;
        sv[tid] = s2 * invT - mean * mean;
        sf[tid] = c * invT;
    }
    __syncthreads();
    if (tid == 0) {
        float vsum = 0.0f, fsum = 0.0f;
        for (int i = 0; i < E_DIM; i++) { vsum += sv[i]; fsum += sf[i]; }
        out[Z_OFF] = (vsum / (float)E_DIM) * 0.001f;
        const float meanf = fsum / (float)E_DIM;
        float a2 = 0.0f;
        for (int i = 0; i < E_DIM; i++) {
            const float d = sf[i] - meanf;
            a2 = fmaf(d, d, a2);
        }
        out[LB_OFF] = (sqrtf(a2 / (float)(E_DIM - 1)) / (meanf + 1e-8f)) * 0.01f;
        g_done = 0;
    }
}

extern "C" void kernel_launch(void* const* d_in, const int* in_sizes, int n_in,
                              void* d_out, int out_size)
{
    const float* hs = (const float*)d_in[0];
    const float* W  = (const float*)d_in[1];
    if (n_in >= 2 && in_sizes[0] < in_sizes[1]) {
        const float* t = hs; hs = W; W = t;
    }
    float* out = (float*)d_out;
    cudaFuncSetAttribute(fused_router_kernel,
                         cudaFuncAttributeMaxDynamicSharedMemorySize, DYN_B);
    wsplit_kernel<<<128, 256>>>(W);
    fused_router_kernel<<<NBLK, NTHR, DYN_B>>>(hs, out);
}

// round 14
// speedup vs baseline: 1.2660x; 1.1577x over previous
#include <cuda_runtime.h>
#include <cuda_fp16.h>
#include <math.h>
#include <stdint.h>

#define T_TOK   16384
#define H_DIM   2048
#define E_DIM   64
#define BM      128
#define KC      64
#define NSTG    (H_DIM / KC)            // 32
#define NBLK    (T_TOK / BM)            // 128
#define NTHR    256

#define W_OFF   0
#define I_OFF   32768
#define L_OFF   65536
#define Z_OFF   1114112
#define LB_OFF  1114113

#define PITCH   144                     // 128B (64 fp16) + 16B pad per row
#define ALTILE  (BM * PITCH)            // 18432 B per A limb
#define ABUF    (2 * ALTILE)            // 36864 B A image (hi|mid)
#define BLTILE  (E_DIM * PITCH)         // 9216 B per B limb
#define BIMG    (2 * BLTILE)            // 18432 B B image (hi|mid)
#define BCHUNKS (BIMG / 16)             // 1152
#define DYN_B   (2 * ABUF + 3 * BIMG)   // 129024 -> 1 CTA/SM

__device__ __align__(256) unsigned char g_wlimb[NSTG * BIMG];  // 576 KB
__device__ float g_partials[NBLK * 3 * E_DIM];
__device__ int   g_done = 0;

__device__ __forceinline__ uint32_t smem_u32(const void* p) {
    uint32_t a;
    asm("{ .reg .u64 t; cvta.to.shared.u64 t, %1; cvt.u32.u64 %0, t; }" : "=r"(a) : "l"(p));
    return a;
}
__device__ __forceinline__ void sts64(uint32_t a, uint32_t x, uint32_t y) {
    asm volatile("st.shared.v2.b32 [%0], {%1, %2};" :: "r"(a), "r"(x), "r"(y));
}
#define LDSM_X4(r0, r1, r2, r3, addr)                                         \
    asm volatile("ldmatrix.sync.aligned.m8n8.x4.shared.b16 {%0,%1,%2,%3}, [%4];" \
                 : "=r"(r0), "=r"(r1), "=r"(r2), "=r"(r3) : "r"(addr))
#define MMA16816(d, a, b)                                                     \
    asm volatile("mma.sync.aligned.m16n8k16.row.col.f32.f16.f16.f32 "         \
                 "{%0,%1,%2,%3}, {%4,%5,%6,%7}, {%8,%9}, {%0,%1,%2,%3};"      \
                 : "+f"((d)[0]), "+f"((d)[1]), "+f"((d)[2]), "+f"((d)[3])     \
                 : "r"((a)[0]), "r"((a)[1]), "r"((a)[2]), "r"((a)[3]),        \
                   "r"((b)[0]), "r"((b)[1]))
#define MMA16816H(d, a, b)                                                    \
    asm volatile("mma.sync.aligned.m16n8k16.row.col.f16.f16.f16.f16 "         \
                 "{%0,%1}, {%2,%3,%4,%5}, {%6,%7}, {%0,%1};"                  \
                 : "+r"((d)[0]), "+r"((d)[1])                                 \
                 : "r"((a)[0]), "r"((a)[1]), "r"((a)[2]), "r"((a)[3]),        \
                   "r"((b)[0]), "r"((b)[1]))
#define CP_ASYNC16(dst, src)                                                  \
    asm volatile("cp.async.ca.shared.global [%0], [%1], 16;" :: "r"(dst), "l"(src))
#define CP_COMMIT()  asm volatile("cp.async.commit_group;" ::: "memory")
#define CP_WAIT(n)   asm volatile("cp.async.wait_group %0;" :: "n"(n) : "memory")

// 2-limb fp16 split: h+m ~ x to 2^-22 rel; residual subtraction exact.
__device__ __forceinline__ void split2(float x0, float x1, uint32_t& h, uint32_t& m) {
    __half2 h2 = __floats2half2_rn(x0, x1);
    h = *reinterpret_cast<uint32_t*>(&h2);
    float2 hf = __half22float2(h2);
    __half2 m2 = __floats2half2_rn(x0 - hf.x, x1 - hf.y);
    m = *reinterpret_cast<uint32_t*>(&m2);
}

// ---- W limb precompute: [E,H] fp32 -> per-stage f16 limb images (PITCH 144) ----
__global__ __launch_bounds__(256, 4)
void wsplit_kernel(const float* __restrict__ W)
{
    const int f  = blockIdx.x * 256 + threadIdx.x;   // float4 id, 0..32767
    const int e  = f >> 9, c = f & 511;
    const int st = c >> 4, q = c & 15;
    float4 v = *(const float4*)(W + (size_t)e * H_DIM + c * 4);
    uint32_t h0, m0, h1, m1;
    split2(v.x, v.y, h0, m0);
    split2(v.z, v.w, h1, m1);
    unsigned char* img = g_wlimb + (size_t)st * BIMG;
    const uint32_t off = (uint32_t)(e * PITCH + q * 8);
    *(uint2*)(img + off)          = make_uint2(h0, h1);
    *(uint2*)(img + BLTILE + off) = make_uint2(m0, m1);
}

struct Frags {
    uint32_t aH[2][4], aM[2][4];   // 2 m-tiles x (4 regs)
    uint32_t bH[8], bM[8];         // 4 n-tiles x (2 regs)
};

__device__ __forceinline__ void load_frags(Frags& f, uint32_t sa, uint32_t sb,
                                           uint32_t a_off, uint32_t b_off, int ks)
{
#pragma unroll
    for (int mt = 0; mt < 2; mt++) {
        LDSM_X4(f.aH[mt][0], f.aH[mt][1], f.aH[mt][2], f.aH[mt][3],
                sa + a_off + (uint32_t)(mt * 16 * PITCH) + ks * 32);
        LDSM_X4(f.aM[mt][0], f.aM[mt][1], f.aM[mt][2], f.aM[mt][3],
                sa + ALTILE + a_off + (uint32_t)(mt * 16 * PITCH) + ks * 32);
    }
#pragma unroll
    for (int np = 0; np < 2; np++) {
        LDSM_X4(f.bH[np * 4 + 0], f.bH[np * 4 + 1], f.bH[np * 4 + 2], f.bH[np * 4 + 3],
                sb + (uint32_t)(np * 16 * PITCH) + b_off + ks * 32);
        LDSM_X4(f.bM[np * 4 + 0], f.bM[np * 4 + 1], f.bM[np * 4 + 2], f.bM[np * 4 + 3],
                sb + BLTILE + (uint32_t)(np * 16 * PITCH) + b_off + ks * 32);
    }
}

__global__ __launch_bounds__(NTHR, 1)
void fused_router_kernel(const float* __restrict__ A, float* __restrict__ out)
{
    extern __shared__ __align__(16) unsigned char dynsm[];
    const uint32_t sbase = smem_u32(dynsm);          // [A0|A1|B0|B1|B2]
    const uint32_t bbase = sbase + 2 * ABUF;

    const int tid  = threadIdx.x;
    const int wid  = tid >> 5;
    const int lane = tid & 31;
    const int row0 = blockIdx.x * BM;

    // A load map: 128 rows x 64 floats = 2048 f4 -> 8 per thread
    int arow[8], ac4[8];
#pragma unroll
    for (int j = 0; j < 8; j++) { int f = tid + j * NTHR; arow[j] = f >> 4; ac4[j] = f & 15; }

    float4 va[8];

    // ---- prologue ----
#pragma unroll
    for (int j = 0; j < 5; j++) {        // B0
        uint32_t cid = (uint32_t)tid + j * NTHR;
        if (cid < BCHUNKS) CP_ASYNC16(bbase + cid * 16, g_wlimb + cid * 16);
    }
    CP_COMMIT();
#pragma unroll
    for (int j = 0; j < 8; j++)          // A0 -> regs
        va[j] = *(const float4*)(A + (size_t)(row0 + arow[j]) * H_DIM + ac4[j] * 4);
#pragma unroll
    for (int j = 0; j < 8; j++) {        // A0 -> Abuf0
        uint32_t h0, m0, h1, m1;
        split2(va[j].x, va[j].y, h0, m0);
        split2(va[j].z, va[j].w, h1, m1);
        const uint32_t off = (uint32_t)(arow[j] * PITCH + ac4[j] * 8);
        sts64(sbase + off, h0, h1);
        sts64(sbase + ALTILE + off, m0, m1);
    }
#pragma unroll
    for (int j = 0; j < 5; j++) {        // B1
        uint32_t cid = (uint32_t)tid + j * NTHR;
        if (cid < BCHUNKS) CP_ASYNC16(bbase + BIMG + cid * 16, g_wlimb + BIMG + cid * 16);
    }
    CP_COMMIT();
#pragma unroll
    for (int j = 0; j < 8; j++)          // A1 -> regs
        va[j] = *(const float4*)(A + (size_t)(row0 + arow[j]) * H_DIM + KC + ac4[j] * 4);

    // warp tile 32x32: mbase = (wid&3)*32, nhalf = wid>>2
    const int mbase = (wid & 3) * 32, nhalf = wid >> 2;
    const uint32_t a_off = (uint32_t)((mbase + (lane & 15)) * PITCH + (lane >> 4) * 16);
    const uint32_t b_off = (uint32_t)((nhalf * 32 + (lane & 7) + ((lane >> 4) & 1) * 8) * PITCH
                                      + ((lane >> 3) & 1) * 16);

    float acc[32];                       // 8 tiles (2mt x 4nt) x 4
#pragma unroll
    for (int i = 0; i < 32; i++) acc[i] = 0.0f;
    uint32_t cacc[16];                   // f16x2 correction accumulators
#pragma unroll
    for (int i = 0; i < 16; i++) cacc[i] = 0u;

    Frags fr[2];

    for (int i = 0; i < NSTG; i++) {
        if (i == NSTG - 1) CP_WAIT(0); else CP_WAIT(1);
        __syncthreads();

        // producer: B_{i+2} cp.async, A_{i+1} split->STS, A_{i+2} LDG
        if (i + 2 < NSTG) {
            const unsigned char* gB = g_wlimb + (size_t)(i + 2) * BIMG;
            const uint32_t dst = bbase + (uint32_t)((i + 2) % 3) * BIMG;
#pragma unroll
            for (int j = 0; j < 5; j++) {
                uint32_t cid = (uint32_t)tid + j * NTHR;
                if (cid < BCHUNKS) CP_ASYNC16(dst + cid * 16, gB + cid * 16);
            }
            CP_COMMIT();
        }
        if (i + 1 < NSTG) {
            const uint32_t da = sbase + (uint32_t)((i + 1) & 1) * ABUF;
#pragma unroll
            for (int j = 0; j < 8; j++) {
                uint32_t h0, m0, h1, m1;
                split2(va[j].x, va[j].y, h0, m0);
                split2(va[j].z, va[j].w, h1, m1);
                const uint32_t off = (uint32_t)(arow[j] * PITCH + ac4[j] * 8);
                sts64(da + off, h0, h1);
                sts64(da + ALTILE + off, m0, m1);
            }
            if (i + 2 < NSTG) {
                const int kt = (i + 2) * KC;
#pragma unroll
                for (int j = 0; j < 8; j++)
                    va[j] = *(const float4*)(A + (size_t)(row0 + arow[j]) * H_DIM + kt + ac4[j] * 4);
            }
        }

        // consumer: 4 k16 steps, register-double-buffered fragments
        const uint32_t sa = sbase + (uint32_t)(i & 1) * ABUF;
        const uint32_t sb = bbase + (uint32_t)(i % 3) * BIMG;
        load_frags(fr[0], sa, sb, a_off, b_off, 0);
#pragma unroll
        for (int ks = 0; ks < 4; ks++) {
            Frags& cur = fr[ks & 1];
            if (ks < 3) load_frags(fr[(ks + 1) & 1], sa, sb, a_off, b_off, ks + 1);
            // hh (f32 acc): 8 independent chains
#pragma unroll
            for (int mt = 0; mt < 2; mt++)
#pragma unroll
                for (int nt = 0; nt < 4; nt++)
                    MMA16816(acc + (mt * 4 + nt) * 4, cur.aH[mt], cur.bH + nt * 2);
            // hm + mh (f16 acc, ~2^-11 of main)
#pragma unroll
            for (int mt = 0; mt < 2; mt++)
#pragma unroll
                for (int nt = 0; nt < 4; nt++)
                    MMA16816H(cacc + (mt * 4 + nt) * 2, cur.aH[mt], cur.bM + nt * 2);
#pragma unroll
            for (int mt = 0; mt < 2; mt++)
#pragma unroll
                for (int nt = 0; nt < 4; nt++)
                    MMA16816H(cacc + (mt * 4 + nt) * 2, cur.aM[mt], cur.bH + nt * 2);
        }
    }
    // merge f16 corrections
#pragma unroll
    for (int t = 0; t < 8; t++) {
        float2 c0 = __half22float2(*reinterpret_cast<__half2*>(&cacc[t * 2 + 0]));
        float2 c1 = __half22float2(*reinterpret_cast<__half2*>(&cacc[t * 2 + 1]));
        acc[t * 4 + 0] += c0.x; acc[t * 4 + 1] += c0.y;
        acc[t * 4 + 2] += c1.x; acc[t * 4 + 3] += c1.y;
    }
    __syncthreads();

    // ---- fused epilogue ----
    float* fsm = (float*)dynsm;                 // [128][68]
    int*   si1 = (int*)(fsm + 128 * 68);
    float* sp1 = (float*)(si1 + 128);
    int*   si2 = (int*)(sp1 + 128);
    float* sp2 = (float*)(si2 + 128);

#pragma unroll
    for (int mt = 0; mt < 2; mt++) {
        const int mrow = mbase + mt * 16 + (lane >> 2);
#pragma unroll
        for (int nt = 0; nt < 4; nt++) {
            const int ncl = nhalf * 32 + nt * 8 + (lane & 3) * 2;
            float* d = acc + (mt * 4 + nt) * 4;
            *(float2*)&fsm[mrow * 68 + ncl] = make_float2(d[0], d[1]);
            *(float2*)&fsm[(mrow + 8) * 68 + ncl] = make_float2(d[2], d[3]);
        }
    }
    __syncthreads();

    if (tid < BM) {
        float lg[64];
#pragma unroll
        for (int c = 0; c < 64; c++) lg[c] = fsm[tid * 68 + c];
        float mx = lg[0];
#pragma unroll
        for (int c = 1; c < 64; c++) mx = fmaxf(mx, lg[c]);
        float se = 0.0f;
#pragma unroll
        for (int c = 0; c < 64; c++) se += expf(lg[c] - mx);
        float v1 = -INFINITY; int i1 = 0;
#pragma unroll
        for (int c = 0; c < 64; c++)
            if (lg[c] > v1) { v1 = lg[c]; i1 = c; }
        float v2 = -INFINITY; int i2 = 0;
#pragma unroll
        for (int c = 0; c < 64; c++)
            if (c != i1 && lg[c] > v2) { v2 = lg[c]; i2 = c; }

        const float p1 = expf(v1 - mx) / se;
        const float p2 = expf(v2 - mx) / se;
        const float inv = 1.0f / (p1 + p2);
        const int t = row0 + tid;
        out[W_OFF + (size_t)t * 2 + 0] = p1 * inv;
        out[W_OFF + (size_t)t * 2 + 1] = p2 * inv;
        out[I_OFF + (size_t)t * 2 + 0] = (float)i1;
        out[I_OFF + (size_t)t * 2 + 1] = (float)i2;
        si1[tid] = i1; sp1[tid] = p1;
        si2[tid] = i2; sp2[tid] = p2;
    }
    __syncthreads();

#pragma unroll
    for (int j = 0; j < 8; j++) {           // coalesced logits store: 2048 f4
        int u = j * NTHR + tid, r = u >> 4, c4 = (u & 15) * 4;
        float4 v = *(float4*)&fsm[r * 68 + c4];
        *(float4*)&out[L_OFF + (size_t)(row0 + r) * 64 + c4] = v;
    }

    if (tid < E_DIM) {                       // deterministic per-block partials
        float s1 = 0.0f, s2 = 0.0f, cc = 0.0f;
        for (int r = 0; r < BM; r++) {
            float v = fsm[r * 68 + tid];
            s1 += v;
            s2 = fmaf(v, v, s2);
            if (si1[r] == tid) cc += sp1[r];
            if (si2[r] == tid) cc += sp2[r];
        }
        const int b = blockIdx.x;
        g_partials[(b * 3 + 0) * E_DIM + tid] = s1;
        g_partials[(b * 3 + 1) * E_DIM + tid] = s2;
        g_partials[(b * 3 + 2) * E_DIM + tid] = cc;
    }

    // ---- fused finalize ----
    __syncthreads();
    __threadfence();
    __shared__ int s_last;
    if (tid == 0) s_last = (atomicAdd(&g_done, 1) == NBLK - 1) ? 1 : 0;
    __syncthreads();
    if (!s_last) return;
    __threadfence();

    float* red = (float*)dynsm;              // [4][3][64]
    {
        const int g = tid >> 6, e = tid & 63;   // 4 groups x 32 blocks
        float s1 = 0.0f, s2 = 0.0f, c = 0.0f;
        for (int b = g * 32; b < g * 32 + 32; b++) {
            s1 += g_partials[(b * 3 + 0) * E_DIM + e];
            s2 += g_partials[(b * 3 + 1) * E_DIM + e];
            c  += g_partials[(b * 3 + 2) * E_DIM + e];
        }
        red[(g * 3 + 0) * 64 + e] = s1;
        red[(g * 3 + 1) * 64 + e] = s2;
        red[(g * 3 + 2) * 64 + e] = c;
    }
    __syncthreads();

    float* sv = red + 12 * 64;
    float* sf = sv + 64;
    if (tid < 64) {
        float s1 = 0.0f, s2 = 0.0f, c = 0.0f;
#pragma unroll
        for (int g = 0; g < 4; g++) {
            s1 += red[(g * 3 + 0) * 64 + tid];
            s2 += red[(g * 3 + 1) * 64 + tid];
            c  += red[(g * 3 + 2) * 64 + tid];
        }
        const float invT = 1.0f / (float)T_TOK;
        const float mean = s1 * invT;
        sv[tid] = s2 * invT - mean * mean;
        sf[tid] = c * invT;
    }
    __syncthreads();
    if (tid == 0) {
        float vsum = 0.0f, fsum = 0.0f;
        for (int i = 0; i < E_DIM; i++) { vsum += sv[i]; fsum += sf[i]; }
        out[Z_OFF] = (vsum / (float)E_DIM) * 0.001f;
        const float meanf = fsum / (float)E_DIM;
        float a2 = 0.0f;
        for (int i = 0; i < E_DIM; i++) {
            const float d = sf[i] - meanf;
            a2 = fmaf(d, d, a2);
        }
        out[LB_OFF] = (sqrtf(a2 / (float)(E_DIM - 1)) / (meanf + 1e-8f)) * 0.01f;
        g_done = 0;
    }
}

extern "C" void kernel_launch(void* const* d_in, const int* in_sizes, int n_in,
                              void* d_out, int out_size)
{
    const float* hs = (const float*)d_in[0];
    const float* W  = (const float*)d_in[1];
    if (n_in >= 2 && in_sizes[0] < in_sizes[1]) {
        const float* t = hs; hs = W; W = t;
    }
    float* out = (float*)d_out;
    cudaFuncSetAttribute(fused_router_kernel,
                         cudaFuncAttributeMaxDynamicSharedMemorySize, DYN_B);
    wsplit_kernel<<<128, 256>>>(W);
    fused_router_kernel<<<NBLK, NTHR, DYN_B>>>(hs, out);
}